// round 1
// baseline (speedup 1.0000x reference)
#include <cuda_runtime.h>
#include <math.h>

#define BB 4
#define SS 2048
#define DD 1024
#define HH 16
#define HDIM 64
#define MM (BB*SS)   // 8192

// Scratch (allocation-free rule: __device__ globals)
__device__ float g_Q[BB*HH*SS*HDIM];   // [B,H,S,HD]
__device__ float g_K[BB*HH*SS*HDIM];
__device__ float g_V[BB*HH*SS*HDIM];
__device__ float g_AO[BB*SS*DD];       // [B,S,D]

// ---------------------------------------------------------------------------
// GEMM: out = X[M,K] @ W[N,K]^T   (M=8192, N=1024, K=1024)
// MODE 0: write g_Q with RoPE (transposed [B,H,S,HD] layout)
// MODE 1: write g_K with RoPE
// MODE 2: write g_V (transpose only)
// MODE 3: X taken from g_AO, plain write to `out` ([M,N])
// Block: 256 threads (16x16), 64x64 tile, 4x4 microtile, BK=16.
// ---------------------------------------------------------------------------
template<int MODE>
__global__ __launch_bounds__(256)
void gemm_kernel(const float* __restrict__ X,
                 const float* __restrict__ W,
                 const float* __restrict__ fc,
                 const float* __restrict__ fs,
                 float* __restrict__ out)
{
    __shared__ float As[16][64];
    __shared__ float Bs[16][64];

    const float* Xp = (MODE == 3) ? g_AO : X;

    const int tx = threadIdx.x & 15;
    const int ty = threadIdx.x >> 4;
    const int m0 = blockIdx.y * 64;
    const int n0 = blockIdx.x * 64;

    float acc[4][4] = {};

    const int idx = threadIdx.x * 4;   // 0..1023
    const int lr  = idx >> 4;          // 0..63  row within tile
    const int lc  = idx & 15;          // 0..12  col within k-slab (step 4)

    for (int k0 = 0; k0 < DD; k0 += 16) {
        float4 a = *(const float4*)&Xp[(size_t)(m0 + lr) * DD + k0 + lc];
        As[lc+0][lr] = a.x; As[lc+1][lr] = a.y; As[lc+2][lr] = a.z; As[lc+3][lr] = a.w;
        float4 b = *(const float4*)&W[(size_t)(n0 + lr) * DD + k0 + lc];
        Bs[lc+0][lr] = b.x; Bs[lc+1][lr] = b.y; Bs[lc+2][lr] = b.z; Bs[lc+3][lr] = b.w;
        __syncthreads();
        #pragma unroll
        for (int kk = 0; kk < 16; kk++) {
            float4 av = *(const float4*)&As[kk][ty*4];
            float4 bv = *(const float4*)&Bs[kk][tx*4];
            float aa[4] = {av.x, av.y, av.z, av.w};
            float bb[4] = {bv.x, bv.y, bv.z, bv.w};
            #pragma unroll
            for (int i = 0; i < 4; i++)
                #pragma unroll
                for (int j = 0; j < 4; j++)
                    acc[i][j] = fmaf(aa[i], bb[j], acc[i][j]);
        }
        __syncthreads();
    }

    // Epilogue
    #pragma unroll
    for (int i = 0; i < 4; i++) {
        const int m = m0 + ty*4 + i;
        const int n = n0 + tx*4;       // multiple of 4 -> RoPE pairs intra-thread
        if (MODE == 3) {
            *(float4*)&out[(size_t)m * DD + n] =
                make_float4(acc[i][0], acc[i][1], acc[i][2], acc[i][3]);
        } else {
            const int b = m / SS;
            const int s = m % SS;
            const int h = n / HDIM;
            const int d = n % HDIM;    // multiple of 4
            float v0 = acc[i][0], v1 = acc[i][1], v2 = acc[i][2], v3 = acc[i][3];
            if (MODE == 0 || MODE == 1) {
                // RoPE: pairs (d,d+1) share freq index d/2
                const int f0 = d >> 1;          // even pair
                const int f1 = (d + 2) >> 1;    // next pair
                float c0 = fc[s*32 + f0], s0 = fs[s*32 + f0];
                float c1 = fc[s*32 + f1], s1 = fs[s*32 + f1];
                float r0 = v0*c0 - v1*s0;
                float r1 = v0*s0 + v1*c0;
                float r2 = v2*c1 - v3*s1;
                float r3 = v2*s1 + v3*c1;
                v0 = r0; v1 = r1; v2 = r2; v3 = r3;
            }
            float* dst = (MODE == 0) ? g_Q : (MODE == 1) ? g_K : g_V;
            size_t o = (((size_t)b*HH + h)*SS + s)*HDIM + d;
            *(float4*)&dst[o] = make_float4(v0, v1, v2, v3);
        }
    }
}

// ---------------------------------------------------------------------------
// Causal attention, one thread per query row, per-thread online softmax.
// Grid: (S/128, B*H). Block: 128 threads. K/V tiles 32x64 in smem.
// ---------------------------------------------------------------------------
__global__ __launch_bounds__(128)
void attn_kernel()
{
    __shared__ float Ks[32][HDIM];   // 8 KB
    __shared__ float Vs[32][HDIM];   // 8 KB

    const int bh = blockIdx.y;               // b*H + h
    const int b  = bh / HH;
    const int h  = bh % HH;
    const int s  = blockIdx.x * 128 + threadIdx.x;

    const float* Qp = g_Q + (((size_t)bh) * SS + s) * HDIM;
    float q[HDIM];
    #pragma unroll
    for (int d = 0; d < HDIM; d++) q[d] = Qp[d];

    float acc[HDIM] = {};
    float mmax = -3.0e38f;
    float l = 0.f;

    const int ktiles = blockIdx.x * 4 + 4;   // cover k <= max s in this block

    for (int kt = 0; kt < ktiles; kt++) {
        const float* Kp = g_K + (((size_t)bh) * SS + kt*32) * HDIM;
        const float* Vp = g_V + (((size_t)bh) * SS + kt*32) * HDIM;
        for (int i = threadIdx.x; i < 32*HDIM/4; i += 128) {
            ((float4*)&Ks[0][0])[i] = ((const float4*)Kp)[i];
            ((float4*)&Vs[0][0])[i] = ((const float4*)Vp)[i];
        }
        __syncthreads();

        float sc[32];
        #pragma unroll
        for (int c = 0; c < 32; c++) {
            float dot = 0.f;
            #pragma unroll
            for (int d = 0; d < HDIM; d += 4) {
                float4 kv = *(const float4*)&Ks[c][d];
                dot = fmaf(q[d+0], kv.x, dot);
                dot = fmaf(q[d+1], kv.y, dot);
                dot = fmaf(q[d+2], kv.z, dot);
                dot = fmaf(q[d+3], kv.w, dot);
            }
            const int kp = kt*32 + c;
            sc[c] = (kp <= s) ? dot * 0.125f : -3.0e38f;
        }

        float tmax = mmax;
        #pragma unroll
        for (int c = 0; c < 32; c++) tmax = fmaxf(tmax, sc[c]);
        const float corr = __expf(mmax - tmax);
        mmax = tmax;
        l *= corr;
        #pragma unroll
        for (int d = 0; d < HDIM; d++) acc[d] *= corr;

        #pragma unroll
        for (int c = 0; c < 32; c++) {
            const float p = __expf(sc[c] - mmax);
            l += p;
            #pragma unroll
            for (int d = 0; d < HDIM; d += 4) {
                float4 vv = *(const float4*)&Vs[c][d];
                acc[d+0] = fmaf(p, vv.x, acc[d+0]);
                acc[d+1] = fmaf(p, vv.y, acc[d+1]);
                acc[d+2] = fmaf(p, vv.z, acc[d+2]);
                acc[d+3] = fmaf(p, vv.w, acc[d+3]);
            }
        }
        __syncthreads();
    }

    const float inv = 1.f / l;
    float* Op = g_AO + ((size_t)(b*SS + s)) * DD + h*HDIM;
    #pragma unroll
    for (int d = 0; d < HDIM; d += 4) {
        *(float4*)&Op[d] = make_float4(acc[d+0]*inv, acc[d+1]*inv,
                                       acc[d+2]*inv, acc[d+3]*inv);
    }
}

// ---------------------------------------------------------------------------
extern "C" void kernel_launch(void* const* d_in, const int* in_sizes, int n_in,
                              void* d_out, int out_size)
{
    const float* x  = (const float*)d_in[0];
    const float* fc = (const float*)d_in[1];
    const float* fs = (const float*)d_in[2];
    const float* wq = (const float*)d_in[3];
    const float* wk = (const float*)d_in[4];
    const float* wv = (const float*)d_in[5];
    const float* wo = (const float*)d_in[6];
    float* out = (float*)d_out;

    dim3 gg(DD/64, MM/64);   // (16, 128)
    dim3 gb(256);

    gemm_kernel<0><<<gg, gb>>>(x, wq, fc, fs, nullptr);
    gemm_kernel<1><<<gg, gb>>>(x, wk, fc, fs, nullptr);
    gemm_kernel<2><<<gg, gb>>>(x, wv, fc, fs, nullptr);

    dim3 ag(SS/128, BB*HH);  // (16, 64)
    attn_kernel<<<ag, 128>>>();

    gemm_kernel<3><<<gg, gb>>>(nullptr, wo, nullptr, nullptr, out);
}

// round 2
// speedup vs baseline: 3.8029x; 3.8029x over previous
#include <cuda_runtime.h>
#include <math.h>
#include <stdint.h>

#define BB 4
#define SS 2048
#define DD 1024
#define HH 16
#define HDIM 64
#define MM (BB*SS)   // 8192

// Scratch (allocation-free rule: __device__ globals)
__device__ float g_Q[(size_t)BB*HH*SS*HDIM];   // [B,H,S,HD]
__device__ float g_K[(size_t)BB*HH*SS*HDIM];
__device__ float g_V[(size_t)BB*HH*SS*HDIM];
__device__ float g_AO[(size_t)MM*DD];          // [B,S,D]

__device__ __forceinline__ uint32_t f2tf(float x) {
    uint32_t r;
    asm("cvt.rna.tf32.f32 %0, %1;" : "=r"(r) : "f"(x));
    return r;
}

// D = A(m16k8) @ B(k8n8) + D, tf32 inputs, f32 accum.
__device__ __forceinline__ void mma8(float* c, const uint32_t* a, const uint32_t* b) {
    asm volatile(
        "mma.sync.aligned.m16n8k8.row.col.f32.tf32.tf32.f32 "
        "{%0,%1,%2,%3},{%4,%5,%6,%7},{%8,%9},{%0,%1,%2,%3};"
        : "+f"(c[0]), "+f"(c[1]), "+f"(c[2]), "+f"(c[3])
        : "r"(a[0]), "r"(a[1]), "r"(a[2]), "r"(a[3]), "r"(b[0]), "r"(b[1]));
}

// ---------------------------------------------------------------------------
// GEMM: out = X[M,K] @ W[N,K]^T   (M=8192, N=1024, K=1024), tf32 tensor cores
// Block 256 thr (8 warps), tile M128 x N64, K-slab 32. Warps 4(M) x 2(N).
// MODE 0/1: Q/K with fused RoPE, transposed write to [B,H,S,HD]
// MODE 2:   V, transposed write
// MODE 3:   X = g_AO, plain [M,N] write to out
// ---------------------------------------------------------------------------
template<int MODE>
__global__ __launch_bounds__(256)
void gemm_tf32(const float* __restrict__ X,
               const float* __restrict__ W,
               const float* __restrict__ fc,
               const float* __restrict__ fs,
               float* __restrict__ out)
{
    __shared__ uint32_t As[128][36];   // [m][k] tf32
    __shared__ uint32_t Bs[64][36];    // [n][k] tf32

    const float* Xp = (MODE == 3) ? g_AO : X;

    const int tid  = threadIdx.x;
    const int m0   = blockIdx.y * 128;
    const int n0   = blockIdx.x * 64;
    const int warp = tid >> 5, lane = tid & 31;
    const int wm   = warp & 3, wn = warp >> 2;
    const int g    = lane >> 2, tig = lane & 3;

    float acc[2][4][4];
    #pragma unroll
    for (int mi = 0; mi < 2; mi++)
        #pragma unroll
        for (int ni = 0; ni < 4; ni++)
            #pragma unroll
            for (int j = 0; j < 4; j++) acc[mi][ni][j] = 0.f;

    for (int k0 = 0; k0 < DD; k0 += 32) {
        #pragma unroll
        for (int t = tid; t < 128 * 8; t += 256) {
            int r = t >> 3, c = (t & 7) * 4;
            float4 v = *(const float4*)&Xp[(size_t)(m0 + r) * DD + k0 + c];
            uint4 u = make_uint4(f2tf(v.x), f2tf(v.y), f2tf(v.z), f2tf(v.w));
            *(uint4*)&As[r][c] = u;
        }
        #pragma unroll
        for (int t = tid; t < 64 * 8; t += 256) {
            int r = t >> 3, c = (t & 7) * 4;
            float4 v = *(const float4*)&W[(size_t)(n0 + r) * DD + k0 + c];
            uint4 u = make_uint4(f2tf(v.x), f2tf(v.y), f2tf(v.z), f2tf(v.w));
            *(uint4*)&Bs[r][c] = u;
        }
        __syncthreads();

        #pragma unroll
        for (int kk = 0; kk < 4; kk++) {
            uint32_t a[2][4], b[4][2];
            #pragma unroll
            for (int mi = 0; mi < 2; mi++) {
                int r = wm * 32 + mi * 16 + g, c = kk * 8 + tig;
                a[mi][0] = As[r][c];     a[mi][1] = As[r + 8][c];
                a[mi][2] = As[r][c + 4]; a[mi][3] = As[r + 8][c + 4];
            }
            #pragma unroll
            for (int ni = 0; ni < 4; ni++) {
                int r = wn * 32 + ni * 8 + g, c = kk * 8 + tig;
                b[ni][0] = Bs[r][c]; b[ni][1] = Bs[r][c + 4];
            }
            #pragma unroll
            for (int mi = 0; mi < 2; mi++)
                #pragma unroll
                for (int ni = 0; ni < 4; ni++)
                    mma8(acc[mi][ni], a[mi], b[ni]);
        }
        __syncthreads();
    }

    // Epilogue. C frag: c0=(g,2t) c1=(g,2t+1) c2=(g+8,2t) c3=(g+8,2t+1)
    #pragma unroll
    for (int mi = 0; mi < 2; mi++) {
        #pragma unroll
        for (int ni = 0; ni < 4; ni++) {
            const int m = m0 + wm * 32 + mi * 16 + g;
            const int n = n0 + wn * 32 + ni * 8 + 2 * tig;
            float c0 = acc[mi][ni][0], c1 = acc[mi][ni][1];
            float c2 = acc[mi][ni][2], c3 = acc[mi][ni][3];
            if (MODE == 3) {
                *(float2*)&out[(size_t)m * DD + n]       = make_float2(c0, c1);
                *(float2*)&out[(size_t)(m + 8) * DD + n] = make_float2(c2, c3);
            } else {
                const int b = m / SS, s = m % SS;          // rows m, m+8 same batch
                const int h = n / HDIM, d = n % HDIM;      // d even
                float v0 = c0, v1 = c1, v2 = c2, v3 = c3;
                if (MODE < 2) {
                    const int f = d >> 1;
                    float cA = fc[s * 32 + f],       sA = fs[s * 32 + f];
                    float cB = fc[(s + 8) * 32 + f], sB = fs[(s + 8) * 32 + f];
                    v0 = c0 * cA - c1 * sA; v1 = c0 * sA + c1 * cA;
                    v2 = c2 * cB - c3 * sB; v3 = c2 * sB + c3 * cB;
                }
                float* dst = (MODE == 0) ? g_Q : (MODE == 1) ? g_K : g_V;
                size_t o = (((size_t)b * HH + h) * SS + s) * HDIM + d;
                *(float2*)&dst[o]            = make_float2(v0, v1);
                *(float2*)&dst[o + 8 * HDIM] = make_float2(v2, v3);   // row s+8
            }
        }
    }
}

// ---------------------------------------------------------------------------
// Flash attention, tf32 mma. 64-query block, 4 warps (16 rows each),
// 64-key tiles. Q frags register-resident; P round-trips smem as tf32.
// Dynamic smem: Ks[64][68] + Vs[64][72] + Ps[64][68] (u32) = 53248 B
// ---------------------------------------------------------------------------
#define KS_STR 68
#define VS_STR 72
#define PS_STR 68

__global__ __launch_bounds__(128)
void attn_tf32()
{
    extern __shared__ uint32_t sm[];
    uint32_t* Ks = sm;                          // [64][KS_STR]
    uint32_t* Vs = sm + 64 * KS_STR;            // [64][VS_STR]  (keys x dims)
    uint32_t* Ps = sm + 64 * KS_STR + 64 * VS_STR; // [64][PS_STR]

    const int tid  = threadIdx.x;
    const int warp = tid >> 5, lane = tid & 31;
    const int g    = lane >> 2, tig = lane & 3;
    const int qb   = blockIdx.x;
    const int bh   = blockIdx.y;
    const size_t base = (size_t)bh * SS * HDIM;

    // Stage Q tile into Ks, lift fragments to registers
    for (int t = tid; t < 64 * 16; t += 128) {
        int r = t >> 4, c = (t & 15) * 4;
        float4 v = *(const float4*)&g_Q[base + (size_t)(qb * 64 + r) * HDIM + c];
        *(uint4*)&Ks[r * KS_STR + c] =
            make_uint4(f2tf(v.x), f2tf(v.y), f2tf(v.z), f2tf(v.w));
    }
    __syncthreads();
    uint32_t aq[8][4];
    #pragma unroll
    for (int kk = 0; kk < 8; kk++) {
        int r = warp * 16 + g, c = kk * 8 + tig;
        aq[kk][0] = Ks[r * KS_STR + c];       aq[kk][1] = Ks[(r + 8) * KS_STR + c];
        aq[kk][2] = Ks[r * KS_STR + c + 4];   aq[kk][3] = Ks[(r + 8) * KS_STR + c + 4];
    }
    __syncthreads();

    float oacc[8][4];
    #pragma unroll
    for (int ni = 0; ni < 8; ni++)
        #pragma unroll
        for (int j = 0; j < 4; j++) oacc[ni][j] = 0.f;
    float m0 = -1e30f, m1 = -1e30f, l0 = 0.f, l1 = 0.f;
    const int row0 = qb * 64 + warp * 16 + g;
    const int row1 = row0 + 8;

    for (int kt = 0; kt <= qb; kt++) {
        // Load K,V tiles (fp32 -> tf32)
        for (int t = tid; t < 64 * 16; t += 128) {
            int r = t >> 4, c = (t & 15) * 4;
            float4 kv = *(const float4*)&g_K[base + (size_t)(kt * 64 + r) * HDIM + c];
            *(uint4*)&Ks[r * KS_STR + c] =
                make_uint4(f2tf(kv.x), f2tf(kv.y), f2tf(kv.z), f2tf(kv.w));
            float4 vv = *(const float4*)&g_V[base + (size_t)(kt * 64 + r) * HDIM + c];
            *(uint4*)&Vs[r * VS_STR + c] =
                make_uint4(f2tf(vv.x), f2tf(vv.y), f2tf(vv.z), f2tf(vv.w));
        }
        __syncthreads();

        // S = Q @ K^T
        float s[8][4];
        #pragma unroll
        for (int ni = 0; ni < 8; ni++)
            #pragma unroll
            for (int j = 0; j < 4; j++) s[ni][j] = 0.f;
        #pragma unroll
        for (int kk = 0; kk < 8; kk++) {
            uint32_t b[8][2];
            #pragma unroll
            for (int ni = 0; ni < 8; ni++) {
                int r = ni * 8 + g, c = kk * 8 + tig;
                b[ni][0] = Ks[r * KS_STR + c];
                b[ni][1] = Ks[r * KS_STR + c + 4];
            }
            #pragma unroll
            for (int ni = 0; ni < 8; ni++) mma8(s[ni], aq[kk], b[ni]);
        }

        // Scale + causal mask (diag tile only) + row max
        const bool diag = (kt == qb);
        float nm0 = m0, nm1 = m1;
        #pragma unroll
        for (int ni = 0; ni < 8; ni++) {
            int col = kt * 64 + ni * 8 + 2 * tig;
            #pragma unroll
            for (int j = 0; j < 4; j++) s[ni][j] *= 0.125f;
            if (diag) {
                if (col     > row0) s[ni][0] = -1e30f;
                if (col + 1 > row0) s[ni][1] = -1e30f;
                if (col     > row1) s[ni][2] = -1e30f;
                if (col + 1 > row1) s[ni][3] = -1e30f;
            }
            nm0 = fmaxf(nm0, fmaxf(s[ni][0], s[ni][1]));
            nm1 = fmaxf(nm1, fmaxf(s[ni][2], s[ni][3]));
        }
        nm0 = fmaxf(nm0, __shfl_xor_sync(0xffffffffu, nm0, 1));
        nm0 = fmaxf(nm0, __shfl_xor_sync(0xffffffffu, nm0, 2));
        nm1 = fmaxf(nm1, __shfl_xor_sync(0xffffffffu, nm1, 1));
        nm1 = fmaxf(nm1, __shfl_xor_sync(0xffffffffu, nm1, 2));
        float corr0 = __expf(m0 - nm0), corr1 = __expf(m1 - nm1);
        m0 = nm0; m1 = nm1;

        float ls0 = 0.f, ls1 = 0.f;
        #pragma unroll
        for (int ni = 0; ni < 8; ni++) {
            float p0 = __expf(s[ni][0] - m0);
            float p1 = __expf(s[ni][1] - m0);
            float p2 = __expf(s[ni][2] - m1);
            float p3 = __expf(s[ni][3] - m1);
            ls0 += p0 + p1; ls1 += p2 + p3;
            int r = warp * 16 + g, c = ni * 8 + 2 * tig;
            *(uint2*)&Ps[r * PS_STR + c]       = make_uint2(f2tf(p0), f2tf(p1));
            *(uint2*)&Ps[(r + 8) * PS_STR + c] = make_uint2(f2tf(p2), f2tf(p3));
        }
        l0 = l0 * corr0 + ls0;
        l1 = l1 * corr1 + ls1;
        #pragma unroll
        for (int ni = 0; ni < 8; ni++) {
            oacc[ni][0] *= corr0; oacc[ni][1] *= corr0;
            oacc[ni][2] *= corr1; oacc[ni][3] *= corr1;
        }
        __syncwarp();

        // O += P @ V
        #pragma unroll
        for (int kk = 0; kk < 8; kk++) {
            uint32_t a[4];
            {
                int r = warp * 16 + g, c = kk * 8 + tig;
                a[0] = Ps[r * PS_STR + c];       a[1] = Ps[(r + 8) * PS_STR + c];
                a[2] = Ps[r * PS_STR + c + 4];   a[3] = Ps[(r + 8) * PS_STR + c + 4];
            }
            uint32_t b[8][2];
            #pragma unroll
            for (int ni = 0; ni < 8; ni++) {
                b[ni][0] = Vs[(kk * 8 + tig) * VS_STR + ni * 8 + g];
                b[ni][1] = Vs[(kk * 8 + tig + 4) * VS_STR + ni * 8 + g];
            }
            #pragma unroll
            for (int ni = 0; ni < 8; ni++) mma8(oacc[ni], a, b[ni]);
        }
        __syncthreads();
    }

    // Finalize: quad-sum l, normalize, write [B,S,D]
    l0 += __shfl_xor_sync(0xffffffffu, l0, 1);
    l0 += __shfl_xor_sync(0xffffffffu, l0, 2);
    l1 += __shfl_xor_sync(0xffffffffu, l1, 1);
    l1 += __shfl_xor_sync(0xffffffffu, l1, 2);
    const float i0 = 1.f / l0, i1 = 1.f / l1;
    const int b = bh >> 4, h = bh & 15;
    #pragma unroll
    for (int ni = 0; ni < 8; ni++) {
        int col = ni * 8 + 2 * tig;
        size_t o0 = ((size_t)(b * SS + row0)) * DD + h * HDIM + col;
        size_t o1 = ((size_t)(b * SS + row1)) * DD + h * HDIM + col;
        *(float2*)&g_AO[o0] = make_float2(oacc[ni][0] * i0, oacc[ni][1] * i0);
        *(float2*)&g_AO[o1] = make_float2(oacc[ni][2] * i1, oacc[ni][3] * i1);
    }
}

// ---------------------------------------------------------------------------
extern "C" void kernel_launch(void* const* d_in, const int* in_sizes, int n_in,
                              void* d_out, int out_size)
{
    const float* x  = (const float*)d_in[0];
    const float* fc = (const float*)d_in[1];
    const float* fs = (const float*)d_in[2];
    const float* wq = (const float*)d_in[3];
    const float* wk = (const float*)d_in[4];
    const float* wv = (const float*)d_in[5];
    const float* wo = (const float*)d_in[6];
    float* out = (float*)d_out;

    const int attn_smem = 64 * (KS_STR + VS_STR + PS_STR) * 4;   // 53248
    cudaFuncSetAttribute(attn_tf32,
                         cudaFuncAttributeMaxDynamicSharedMemorySize, attn_smem);

    dim3 gg(DD / 64, MM / 128);   // (16, 64)
    gemm_tf32<0><<<gg, 256>>>(x, wq, fc, fs, nullptr);
    gemm_tf32<1><<<gg, 256>>>(x, wk, fc, fs, nullptr);
    gemm_tf32<2><<<gg, 256>>>(x, wv, fc, fs, nullptr);

    dim3 ag(SS / 64, BB * HH);    // (32, 64)
    attn_tf32<<<ag, 128, attn_smem>>>();

    gemm_tf32<3><<<gg, 256>>>(nullptr, wo, nullptr, nullptr, out);
}

// round 7
// speedup vs baseline: 4.7857x; 1.2584x over previous
#include <cuda_runtime.h>
#include <stdint.h>

#define BB 4
#define SS 2048
#define DD 1024
#define HH 16
#define HDIM 64
#define MM (BB*SS)   // 8192

// Scratch (allocation-free rule: __device__ globals). All tf32 bit patterns.
__device__ uint32_t g_Xt[(size_t)MM*DD];
__device__ uint32_t g_Wt[(size_t)4*DD*DD];    // wq,wk,wv,wo
__device__ uint32_t g_Q [(size_t)MM*DD];      // [B,H,S,HD]
__device__ uint32_t g_K [(size_t)MM*DD];
__device__ uint32_t g_V [(size_t)MM*DD];
__device__ uint32_t g_AO[(size_t)MM*DD];      // [B,S,D]

__device__ __forceinline__ uint32_t f2tf(float x) {
    uint32_t r;
    asm("cvt.rna.tf32.f32 %0, %1;" : "=r"(r) : "f"(x));
    return r;
}
__device__ __forceinline__ float ex2(float x) {
    float r;
    asm("ex2.approx.f32 %0, %1;" : "=f"(r) : "f"(x));
    return r;
}
__device__ __forceinline__ void mma8(float* c, const uint32_t* a, const uint32_t* b) {
    asm volatile(
        "mma.sync.aligned.m16n8k8.row.col.f32.tf32.tf32.f32 "
        "{%0,%1,%2,%3},{%4,%5,%6,%7},{%8,%9},{%0,%1,%2,%3};"
        : "+f"(c[0]), "+f"(c[1]), "+f"(c[2]), "+f"(c[3])
        : "r"(a[0]), "r"(a[1]), "r"(a[2]), "r"(a[3]), "r"(b[0]), "r"(b[1]));
}
__device__ __forceinline__ void cpa16(uint32_t dst, const void* src) {
    asm volatile("cp.async.cg.shared.global [%0], [%1], 16;" :: "r"(dst), "l"(src));
}
__device__ __forceinline__ void cpcommit() {
    asm volatile("cp.async.commit_group;");
}
template<int N> __device__ __forceinline__ void cpwait() {
    asm volatile("cp.async.wait_group %0;" :: "n"(N));
}

// ---------------------------------------------------------------------------
// Prepass: fp32 -> tf32 (RNA), same rounding point as Round 2.
// T=0: x -> g_Xt ; T=1..4: w -> g_Wt quadrant
// ---------------------------------------------------------------------------
template<int T>
__global__ void cvt_k(const float4* __restrict__ in, int n4) {
    uint32_t* dst = (T == 0) ? g_Xt : g_Wt + (size_t)(T - 1) * DD * DD;
    int i = blockIdx.x * 256 + threadIdx.x;
    if (i < n4) {
        float4 v = in[i];
        *(uint4*)&dst[(size_t)i * 4] =
            make_uint4(f2tf(v.x), f2tf(v.y), f2tf(v.z), f2tf(v.w));
    }
}

// ---------------------------------------------------------------------------
// GEMM: out = A[M,K] @ W[N,K]^T, tf32 operands pre-converted.
// 128x128 tile, BK=32, 2-stage cp.async, 8 warps (wm 0..3, wn 0..1; 32x64).
// Smem (words): A stage s at s*4608, B stage s at 9216+s*4608; stride 36.
// MODE 0/1: Q/K + RoPE -> [B,H,S,HD] tf32 ; MODE 2: V ; MODE 3: g_AO@wo -> out fp32
// ---------------------------------------------------------------------------
template<int MODE>
__device__ __forceinline__ void gemm_load(uint32_t smb, int stage,
                                          const uint32_t* Ag, const uint32_t* Bg,
                                          int m0, int n0, int k0, int tid) {
    uint32_t sa = smb + (uint32_t)(stage * 4608) * 4u;
    uint32_t sb = smb + (uint32_t)(9216 + stage * 4608) * 4u;
    #pragma unroll
    for (int i = 0; i < 4; i++) {
        int cid = tid + i * 256;
        int r = cid >> 3, c4 = (cid & 7) * 4;
        cpa16(sa + (uint32_t)(r * 36 + c4) * 4u, Ag + (size_t)(m0 + r) * DD + k0 + c4);
        cpa16(sb + (uint32_t)(r * 36 + c4) * 4u, Bg + (size_t)(n0 + r) * DD + k0 + c4);
    }
}

template<int MODE>
__global__ __launch_bounds__(256, 2)
void gemm_tc(const float* __restrict__ fc, const float* __restrict__ fs,
             float* __restrict__ out)
{
    extern __shared__ uint32_t sm[];
    const uint32_t* Ag = (MODE == 3) ? g_AO : g_Xt;
    const uint32_t* Bg = g_Wt + (size_t)MODE * DD * DD;

    const int tid = threadIdx.x;
    const int m0 = blockIdx.y * 128, n0 = blockIdx.x * 128;
    const int warp = tid >> 5, lane = tid & 31;
    const int wm = warp & 3, wn = warp >> 2;
    const int g = lane >> 2, tig = lane & 3;
    const uint32_t smb = (uint32_t)__cvta_generic_to_shared(sm);

    float acc[2][8][4];
    #pragma unroll
    for (int mi = 0; mi < 2; mi++)
        #pragma unroll
        for (int ni = 0; ni < 8; ni++)
            #pragma unroll
            for (int j = 0; j < 4; j++) acc[mi][ni][j] = 0.f;

    gemm_load<MODE>(smb, 0, Ag, Bg, m0, n0, 0, tid);
    cpcommit();

    for (int t = 0; t < 32; t++) {
        const int s = t & 1;
        if (t < 31) {
            gemm_load<MODE>(smb, s ^ 1, Ag, Bg, m0, n0, (t + 1) * 32, tid);
            cpcommit();
            cpwait<1>();
        } else {
            cpwait<0>();
        }
        __syncthreads();

        const uint32_t* As = sm + s * 4608;
        const uint32_t* Bs = sm + 9216 + s * 4608;
        #pragma unroll
        for (int kk = 0; kk < 4; kk++) {
            uint32_t a[2][4], b[8][2];
            #pragma unroll
            for (int mi = 0; mi < 2; mi++) {
                int r = wm * 32 + mi * 16 + g, c = kk * 8 + tig;
                a[mi][0] = As[r * 36 + c];           a[mi][1] = As[(r + 8) * 36 + c];
                a[mi][2] = As[r * 36 + c + 4];       a[mi][3] = As[(r + 8) * 36 + c + 4];
            }
            #pragma unroll
            for (int ni = 0; ni < 8; ni++) {
                int r = wn * 64 + ni * 8 + g, c = kk * 8 + tig;
                b[ni][0] = Bs[r * 36 + c];
                b[ni][1] = Bs[r * 36 + c + 4];
            }
            #pragma unroll
            for (int mi = 0; mi < 2; mi++)
                #pragma unroll
                for (int ni = 0; ni < 8; ni++)
                    mma8(acc[mi][ni], a[mi], b[ni]);
        }
        __syncthreads();
    }

    // Epilogue. C frag: c0=(g,n) c1=(g,n+1) c2=(g+8,n) c3=(g+8,n+1), n even.
    #pragma unroll
    for (int mi = 0; mi < 2; mi++) {
        #pragma unroll
        for (int ni = 0; ni < 8; ni++) {
            const int m = m0 + wm * 32 + mi * 16 + g;
            const int n = n0 + wn * 64 + ni * 8 + 2 * tig;
            float c0 = acc[mi][ni][0], c1 = acc[mi][ni][1];
            float c2 = acc[mi][ni][2], c3 = acc[mi][ni][3];
            if (MODE == 3) {
                *(float2*)&out[(size_t)m * DD + n]       = make_float2(c0, c1);
                *(float2*)&out[(size_t)(m + 8) * DD + n] = make_float2(c2, c3);
            } else {
                const int b = m >> 11, s = m & (SS - 1);
                const int h = n >> 6, d = n & 63;
                float v0 = c0, v1 = c1, v2 = c2, v3 = c3;
                if (MODE < 2) {
                    const int f = d >> 1;
                    float cA = fc[s * 32 + f],       sA = fs[s * 32 + f];
                    float cB = fc[(s + 8) * 32 + f], sB = fs[(s + 8) * 32 + f];
                    v0 = c0 * cA - c1 * sA; v1 = c0 * sA + c1 * cA;
                    v2 = c2 * cB - c3 * sB; v3 = c2 * sB + c3 * cB;
                }
                uint32_t* dst = (MODE == 0) ? g_Q : (MODE == 1) ? g_K : g_V;
                size_t o = (((size_t)b * HH + h) * SS + s) * HDIM + d;
                *(uint2*)&dst[o]             = make_uint2(f2tf(v0), f2tf(v1));
                *(uint2*)&dst[o + 8 * HDIM]  = make_uint2(f2tf(v2), f2tf(v3));
            }
        }
    }
}

// ---------------------------------------------------------------------------
// Flash attention. 256 thr = 2 q-groups x 4 warps; 128 q rows/CTA; 64-key
// tiles, cp.async double-buffered K/V. P passed to PV mma via shfl permute.
// Smem (words): Ks[s] at s*4352 (stride 68), Vs[s] at 8704+s*4608 (stride 72).
// Total 71680 B.
// ---------------------------------------------------------------------------
__device__ __forceinline__ void attn_load(uint32_t smb, int stage,
                                          const uint32_t* Kg, const uint32_t* Vg,
                                          int kt, int tid) {
    uint32_t ks = smb + (uint32_t)(stage * 4352) * 4u;
    uint32_t vs = smb + (uint32_t)(8704 + stage * 4608) * 4u;
    const uint32_t* K0 = Kg + (size_t)kt * 64 * HDIM;
    const uint32_t* V0 = Vg + (size_t)kt * 64 * HDIM;
    #pragma unroll
    for (int i = 0; i < 4; i++) {
        int cid = tid + i * 256;
        int r = cid >> 4, c4 = (cid & 15) * 4;
        cpa16(ks + (uint32_t)(r * 68 + c4) * 4u, K0 + r * HDIM + c4);
        cpa16(vs + (uint32_t)(r * 72 + c4) * 4u, V0 + r * HDIM + c4);
    }
}

#define SCL 0.18033688f   // 0.125 * log2(e)

__global__ __launch_bounds__(256, 2)
void attn_tc()
{
    extern __shared__ uint32_t sm[];
    const int tid = threadIdx.x, warp = tid >> 5, lane = tid & 31;
    const int g = lane >> 2, tig = lane & 3;
    const int gid = warp >> 2, w4 = warp & 3;
    const int qb = blockIdx.x, bh = blockIdx.y;
    const size_t base = (size_t)bh * SS * HDIM;
    const int mylim = 2 * qb + gid;
    const int lim = 2 * qb + 1;
    const int row0 = qb * 128 + gid * 64 + w4 * 16 + g;
    const int row1 = row0 + 8;
    const uint32_t smb = (uint32_t)__cvta_generic_to_shared(sm);

    // Q fragments direct from gmem (already tf32)
    uint32_t aq[8][4];
    {
        const uint32_t* Q0 = g_Q + base + (size_t)row0 * HDIM;
        #pragma unroll
        for (int kk = 0; kk < 8; kk++) {
            aq[kk][0] = Q0[kk * 8 + tig];
            aq[kk][1] = Q0[8 * HDIM + kk * 8 + tig];
            aq[kk][2] = Q0[kk * 8 + tig + 4];
            aq[kk][3] = Q0[8 * HDIM + kk * 8 + tig + 4];
        }
    }

    float oacc[8][4];
    #pragma unroll
    for (int ni = 0; ni < 8; ni++)
        #pragma unroll
        for (int j = 0; j < 4; j++) oacc[ni][j] = 0.f;
    float m0 = -1e30f, m1 = -1e30f, l0 = 0.f, l1 = 0.f;

    const uint32_t* Kg = g_K + base;
    const uint32_t* Vg = g_V + base;
    const int srcA = (lane & 28) | (tig >> 1);
    const int srcB = srcA + 2;
    const bool odd = tig & 1;

    attn_load(smb, 0, Kg, Vg, 0, tid);
    cpcommit();

    for (int kt = 0; kt <= lim; kt++) {
        const int s = kt & 1;
        if (kt < lim) {
            attn_load(smb, s ^ 1, Kg, Vg, kt + 1, tid);
            cpcommit();
            cpwait<1>();
        } else {
            cpwait<0>();
        }
        __syncthreads();

        if (kt <= mylim) {
            const uint32_t* Ks = sm + s * 4352;
            const uint32_t* Vs = sm + 8704 + s * 4608;

            // S = Q @ K^T
            float sc[8][4];
            #pragma unroll
            for (int ni = 0; ni < 8; ni++)
                #pragma unroll
                for (int j = 0; j < 4; j++) sc[ni][j] = 0.f;
            #pragma unroll
            for (int kk = 0; kk < 8; kk++) {
                uint32_t b[8][2];
                #pragma unroll
                for (int ni = 0; ni < 8; ni++) {
                    int r = ni * 8 + g, c = kk * 8 + tig;
                    b[ni][0] = Ks[r * 68 + c];
                    b[ni][1] = Ks[r * 68 + c + 4];
                }
                #pragma unroll
                for (int ni = 0; ni < 8; ni++) mma8(sc[ni], aq[kk], b[ni]);
            }

            // scale (log2 domain) + causal mask on diagonal tile + row max
            const bool diag = (kt == mylim);
            float nm0 = m0, nm1 = m1;
            #pragma unroll
            for (int ni = 0; ni < 8; ni++) {
                int col = kt * 64 + ni * 8 + 2 * tig;
                #pragma unroll
                for (int j = 0; j < 4; j++) sc[ni][j] *= SCL;
                if (diag) {
                    if (col     > row0) sc[ni][0] = -1e30f;
                    if (col + 1 > row0) sc[ni][1] = -1e30f;
                    if (col     > row1) sc[ni][2] = -1e30f;
                    if (col + 1 > row1) sc[ni][3] = -1e30f;
                }
                nm0 = fmaxf(nm0, fmaxf(sc[ni][0], sc[ni][1]));
                nm1 = fmaxf(nm1, fmaxf(sc[ni][2], sc[ni][3]));
            }
            nm0 = fmaxf(nm0, __shfl_xor_sync(0xffffffffu, nm0, 1));
            nm0 = fmaxf(nm0, __shfl_xor_sync(0xffffffffu, nm0, 2));
            nm1 = fmaxf(nm1, __shfl_xor_sync(0xffffffffu, nm1, 1));
            nm1 = fmaxf(nm1, __shfl_xor_sync(0xffffffffu, nm1, 2));
            const float corr0 = ex2(m0 - nm0), corr1 = ex2(m1 - nm1);
            m0 = nm0; m1 = nm1;

            // exp + build PV A-fragments via shfl permutation
            uint32_t pa[8][4];
            float ls0 = 0.f, ls1 = 0.f;
            #pragma unroll
            for (int ni = 0; ni < 8; ni++) {
                float p0 = ex2(sc[ni][0] - m0);
                float p1 = ex2(sc[ni][1] - m0);
                float p2 = ex2(sc[ni][2] - m1);
                float p3 = ex2(sc[ni][3] - m1);
                ls0 += p0 + p1; ls1 += p2 + p3;
                uint32_t q0 = f2tf(p0), q1 = f2tf(p1);
                uint32_t q2 = f2tf(p2), q3 = f2tf(p3);
                uint32_t u0 = __shfl_sync(0xffffffffu, q0, srcA);
                uint32_t u1 = __shfl_sync(0xffffffffu, q1, srcA);
                uint32_t u2 = __shfl_sync(0xffffffffu, q2, srcA);
                uint32_t u3 = __shfl_sync(0xffffffffu, q3, srcA);
                uint32_t v0 = __shfl_sync(0xffffffffu, q0, srcB);
                uint32_t v1 = __shfl_sync(0xffffffffu, q1, srcB);
                uint32_t v2 = __shfl_sync(0xffffffffu, q2, srcB);
                uint32_t v3 = __shfl_sync(0xffffffffu, q3, srcB);
                pa[ni][0] = odd ? u1 : u0;
                pa[ni][1] = odd ? u3 : u2;
                pa[ni][2] = odd ? v1 : v0;
                pa[ni][3] = odd ? v3 : v2;
            }
            l0 = l0 * corr0 + ls0;
            l1 = l1 * corr1 + ls1;
            #pragma unroll
            for (int ni = 0; ni < 8; ni++) {
                oacc[ni][0] *= corr0; oacc[ni][1] *= corr0;
                oacc[ni][2] *= corr1; oacc[ni][3] *= corr1;
            }

            // O += P @ V
            #pragma unroll
            for (int kk = 0; kk < 8; kk++) {
                uint32_t b[8][2];
                #pragma unroll
                for (int ni = 0; ni < 8; ni++) {
                    b[ni][0] = Vs[(kk * 8 + tig) * 72 + ni * 8 + g];
                    b[ni][1] = Vs[(kk * 8 + tig + 4) * 72 + ni * 8 + g];
                }
                #pragma unroll
                for (int ni = 0; ni < 8; ni++) mma8(oacc[ni], pa[kk], b[ni]);
            }
        }
        __syncthreads();
    }

    // Finalize
    l0 += __shfl_xor_sync(0xffffffffu, l0, 1);
    l0 += __shfl_xor_sync(0xffffffffu, l0, 2);
    l1 += __shfl_xor_sync(0xffffffffu, l1, 1);
    l1 += __shfl_xor_sync(0xffffffffu, l1, 2);
    const float i0 = 1.f / l0, i1 = 1.f / l1;
    const int b = bh >> 4, h = bh & 15;
    #pragma unroll
    for (int ni = 0; ni < 8; ni++) {
        int col = ni * 8 + 2 * tig;
        size_t o0 = ((size_t)(b * SS + row0)) * DD + h * HDIM + col;
        size_t o1 = ((size_t)(b * SS + row1)) * DD + h * HDIM + col;
        *(uint2*)&g_AO[o0] = make_uint2(f2tf(oacc[ni][0] * i0), f2tf(oacc[ni][1] * i0));
        *(uint2*)&g_AO[o1] = make_uint2(f2tf(oacc[ni][2] * i1), f2tf(oacc[ni][3] * i1));
    }
}

// ---------------------------------------------------------------------------
extern "C" void kernel_launch(void* const* d_in, const int* in_sizes, int n_in,
                              void* d_out, int out_size)
{
    const float* x  = (const float*)d_in[0];
    const float* fc = (const float*)d_in[1];
    const float* fs = (const float*)d_in[2];
    float* out = (float*)d_out;

    const int gemm_smem = 18432 * 4;   // 73728
    const int attn_smem = 17920 * 4;   // 71680
    cudaFuncSetAttribute(gemm_tc<0>, cudaFuncAttributeMaxDynamicSharedMemorySize, gemm_smem);
    cudaFuncSetAttribute(gemm_tc<1>, cudaFuncAttributeMaxDynamicSharedMemorySize, gemm_smem);
    cudaFuncSetAttribute(gemm_tc<2>, cudaFuncAttributeMaxDynamicSharedMemorySize, gemm_smem);
    cudaFuncSetAttribute(gemm_tc<3>, cudaFuncAttributeMaxDynamicSharedMemorySize, gemm_smem);
    cudaFuncSetAttribute(attn_tc,    cudaFuncAttributeMaxDynamicSharedMemorySize, attn_smem);

    // Prepass: convert inputs to tf32 (same RNA rounding as Round 2)
    const int n4x = MM * DD / 4;       // 2097152
    const int n4w = DD * DD / 4;       // 262144
    cvt_k<0><<<n4x / 256, 256>>>((const float4*)x, n4x);
    cvt_k<1><<<n4w / 256, 256>>>((const float4*)d_in[3], n4w);
    cvt_k<2><<<n4w / 256, 256>>>((const float4*)d_in[4], n4w);
    cvt_k<3><<<n4w / 256, 256>>>((const float4*)d_in[5], n4w);
    cvt_k<4><<<n4w / 256, 256>>>((const float4*)d_in[6], n4w);

    dim3 gg(DD / 128, MM / 128);       // (8, 64)
    gemm_tc<0><<<gg, 256, gemm_smem>>>(fc, fs, nullptr);
    gemm_tc<1><<<gg, 256, gemm_smem>>>(fc, fs, nullptr);
    gemm_tc<2><<<gg, 256, gemm_smem>>>(fc, fs, nullptr);

    dim3 ag(SS / 128, BB * HH);        // (16, 64)
    attn_tc<<<ag, 256, attn_smem>>>();

    gemm_tc<3><<<gg, 256, gemm_smem>>>(nullptr, nullptr, out);
}

// round 10
// speedup vs baseline: 8.9669x; 1.8737x over previous
#include <cuda_runtime.h>
#include <cuda_fp16.h>
#include <stdint.h>

#define BB 4
#define SS 2048
#define DD 1024
#define HH 16
#define HDIM 64
#define MM (BB*SS)   // 8192

// Scratch (allocation-free rule: __device__ globals). All fp16.
__device__ __half g_Xt[(size_t)MM*DD];
__device__ __half g_Wt[(size_t)4*DD*DD];    // wq,wk,wv,wo
__device__ __half g_Q [(size_t)MM*DD];      // [B,H,S,HD]
__device__ __half g_K [(size_t)MM*DD];
__device__ __half g_V [(size_t)MM*DD];      // TRANSPOSED: [B,H,HD,S]
__device__ __half g_AO[(size_t)MM*DD];      // [B,S,D]

__device__ __forceinline__ float ex2(float x) {
    float r;
    asm("ex2.approx.f32 %0, %1;" : "=f"(r) : "f"(x));
    return r;
}
__device__ __forceinline__ uint32_t h2(float a, float b) {
    __half2 h = __floats2half2_rn(a, b);
    return *(uint32_t*)&h;
}
// D += A(m16k16) @ B(k16n8), fp16 in, fp32 accum
__device__ __forceinline__ void mmaf16(float* c, const uint32_t* a, const uint32_t* b) {
    asm volatile(
        "mma.sync.aligned.m16n8k16.row.col.f32.f16.f16.f32 "
        "{%0,%1,%2,%3},{%4,%5,%6,%7},{%8,%9},{%0,%1,%2,%3};"
        : "+f"(c[0]), "+f"(c[1]), "+f"(c[2]), "+f"(c[3])
        : "r"(a[0]), "r"(a[1]), "r"(a[2]), "r"(a[3]), "r"(b[0]), "r"(b[1]));
}
__device__ __forceinline__ void cpa16(uint32_t dst, const void* src) {
    asm volatile("cp.async.cg.shared.global [%0], [%1], 16;" :: "r"(dst), "l"(src));
}
__device__ __forceinline__ void cpcommit() {
    asm volatile("cp.async.commit_group;");
}
template<int N> __device__ __forceinline__ void cpwait() {
    asm volatile("cp.async.wait_group %0;" :: "n"(N));
}

// ---------------------------------------------------------------------------
// Prepass: fp32 -> fp16 (RN). T=0: x ; T=1..4: weights.
// ---------------------------------------------------------------------------
template<int T>
__global__ void cvt_k(const float4* __restrict__ in, int n4) {
    __half* dst = (T == 0) ? g_Xt : g_Wt + (size_t)(T - 1) * DD * DD;
    int i = blockIdx.x * 256 + threadIdx.x;
    if (i < n4) {
        float4 v = in[i];
        uint2 o = make_uint2(h2(v.x, v.y), h2(v.z, v.w));
        *(uint2*)&dst[(size_t)i * 4] = o;
    }
}

// ---------------------------------------------------------------------------
// GEMM: out = A[M,K] @ W[N,K]^T, fp16 in, fp32 accum.
// 128x128 tile, K-slab 64, 2-stage cp.async, 8 warps (wm 0..3, wn 0..1).
// Smem halfs: stage s at s*18432; A rows stride 72 halfs, B at +9216 halfs.
// MODE 0/1: Q/K + RoPE -> [B,H,S,HD] ; MODE 2: V -> transposed [B,H,HD,S]
// MODE 3: g_AO @ wo -> fp32 out
// ---------------------------------------------------------------------------
__device__ __forceinline__ void g_load(uint32_t smb, int s,
                                       const __half* Ag, const __half* Bg,
                                       int m0, int n0, int k0, int tid) {
    uint32_t sa = smb + (uint32_t)s * 36864u;
    uint32_t sb = sa + 18432u;
    #pragma unroll
    for (int i = 0; i < 4; i++) {
        int c = tid + i * 256;
        int r = c >> 3, cb = (c & 7) * 16;
        cpa16(sa + (uint32_t)(r * 144 + cb), Ag + (size_t)(m0 + r) * DD + k0 + (c & 7) * 8);
    }
    #pragma unroll
    for (int i = 0; i < 4; i++) {
        int c = tid + i * 256;
        int r = c >> 3, cb = (c & 7) * 16;
        cpa16(sb + (uint32_t)(r * 144 + cb), Bg + (size_t)(n0 + r) * DD + k0 + (c & 7) * 8);
    }
    cpcommit();
}

template<int MODE>
__global__ __launch_bounds__(256, 2)
void gemm_f16(const float* __restrict__ fc, const float* __restrict__ fs,
              float* __restrict__ out)
{
    extern __shared__ __half smh[];
    const __half* Ag = (MODE == 3) ? g_AO : g_Xt;
    const __half* Bg = g_Wt + (size_t)MODE * DD * DD;

    const int tid = threadIdx.x;
    const int m0 = blockIdx.y * 128, n0 = blockIdx.x * 128;
    const int warp = tid >> 5, lane = tid & 31;
    const int wm = warp & 3, wn = warp >> 2;
    const int g = lane >> 2, tig = lane & 3;
    const uint32_t smb = (uint32_t)__cvta_generic_to_shared(smh);

    float acc[2][8][4];
    #pragma unroll
    for (int mi = 0; mi < 2; mi++)
        #pragma unroll
        for (int ni = 0; ni < 8; ni++)
            #pragma unroll
            for (int j = 0; j < 4; j++) acc[mi][ni][j] = 0.f;

    g_load(smb, 0, Ag, Bg, m0, n0, 0, tid);

    for (int t = 0; t < 16; t++) {
        const int s = t & 1;
        if (t < 15) {
            g_load(smb, s ^ 1, Ag, Bg, m0, n0, (t + 1) * 64, tid);
            cpwait<1>();
        } else {
            cpwait<0>();
        }
        __syncthreads();

        const __half* As = smh + s * 18432;
        const __half* Bs = As + 9216;
        #pragma unroll
        for (int ks = 0; ks < 4; ks++) {
            uint32_t a[2][4], b[8][2];
            #pragma unroll
            for (int mi = 0; mi < 2; mi++) {
                int cb = (wm * 32 + mi * 16 + g) * 72 + ks * 16 + 2 * tig;
                a[mi][0] = *(const uint32_t*)&As[cb];
                a[mi][1] = *(const uint32_t*)&As[cb + 8 * 72];
                a[mi][2] = *(const uint32_t*)&As[cb + 8];
                a[mi][3] = *(const uint32_t*)&As[cb + 8 * 72 + 8];
            }
            #pragma unroll
            for (int ni = 0; ni < 8; ni++) {
                int cb = (wn * 64 + ni * 8 + g) * 72 + ks * 16 + 2 * tig;
                b[ni][0] = *(const uint32_t*)&Bs[cb];
                b[ni][1] = *(const uint32_t*)&Bs[cb + 8];
            }
            #pragma unroll
            for (int mi = 0; mi < 2; mi++)
                #pragma unroll
                for (int ni = 0; ni < 8; ni++)
                    mmaf16(acc[mi][ni], a[mi], b[ni]);
        }
        __syncthreads();
    }

    // Epilogue. C frag: c0=(g,n) c1=(g,n+1) c2=(g+8,n) c3=(g+8,n+1), n even.
    #pragma unroll
    for (int mi = 0; mi < 2; mi++) {
        #pragma unroll
        for (int ni = 0; ni < 8; ni++) {
            const int m = m0 + wm * 32 + mi * 16 + g;
            const int n = n0 + wn * 64 + ni * 8 + 2 * tig;
            float c0 = acc[mi][ni][0], c1 = acc[mi][ni][1];
            float c2 = acc[mi][ni][2], c3 = acc[mi][ni][3];
            if (MODE == 3) {
                *(float2*)&out[(size_t)m * DD + n]       = make_float2(c0, c1);
                *(float2*)&out[(size_t)(m + 8) * DD + n] = make_float2(c2, c3);
            } else {
                const int b = m >> 11, sl = m & (SS - 1);
                const int h = n >> 6, d = n & 63;
                const int bh = b * HH + h;
                if (MODE == 2) {
                    // transposed V: [bh][d][s]
                    size_t ov = ((size_t)bh * HDIM + d) * SS + sl;
                    g_V[ov]          = __float2half_rn(c0);
                    g_V[ov + SS]     = __float2half_rn(c1);
                    g_V[ov + 8]      = __float2half_rn(c2);
                    g_V[ov + SS + 8] = __float2half_rn(c3);
                } else {
                    const int f = d >> 1;
                    float cA = fc[sl * 32 + f],       sA = fs[sl * 32 + f];
                    float cB = fc[(sl + 8) * 32 + f], sB = fs[(sl + 8) * 32 + f];
                    float v0 = c0 * cA - c1 * sA, v1 = c0 * sA + c1 * cA;
                    float v2 = c2 * cB - c3 * sB, v3 = c2 * sB + c3 * cB;
                    __half* dstq = (MODE == 0) ? g_Q : g_K;
                    size_t o = ((size_t)bh * SS + sl) * HDIM + d;
                    *(uint32_t*)&dstq[o]            = h2(v0, v1);
                    *(uint32_t*)&dstq[o + 8 * HDIM] = h2(v2, v3);
                }
            }
        }
    }
}

// ---------------------------------------------------------------------------
// Flash attention fp16. 256 thr = 2 q-groups x 4 warps; 128 q rows/CTA;
// 64-key tiles double-buffered. P stays in registers (fp16 C->A identity).
// Smem halfs: Ks[s] at s*4608 (64 keys x 72), Vt[s] at 9216 + s*4608
// (64 dims x 72: transposed V). Total 36864 B.
// ---------------------------------------------------------------------------
__device__ __forceinline__ void attn_load(uint32_t smb, int stage,
                                          const __half* Kg, const __half* Vtg,
                                          int kt, int tid) {
    uint32_t ks = smb + (uint32_t)stage * 9216u;
    uint32_t vs = smb + 18432u + (uint32_t)stage * 9216u;
    #pragma unroll
    for (int i = 0; i < 2; i++) {
        int c = tid + i * 256;
        int r = c >> 3, cb = (c & 7) * 16;
        cpa16(ks + (uint32_t)(r * 144 + cb), Kg + (size_t)(kt * 64 + r) * HDIM + (c & 7) * 8);
        cpa16(vs + (uint32_t)(r * 144 + cb), Vtg + (size_t)r * SS + kt * 64 + (c & 7) * 8);
    }
}

#define SCL 0.18033688f   // 0.125 * log2(e)

__global__ __launch_bounds__(256, 2)
void attn_f16()
{
    extern __shared__ __half smh[];
    const int tid = threadIdx.x, warp = tid >> 5, lane = tid & 31;
    const int g = lane >> 2, tig = lane & 3;
    const int gid = warp >> 2, w4 = warp & 3;
    const int qb = blockIdx.x, bh = blockIdx.y;
    const size_t base = (size_t)bh * SS * HDIM;   // same size for K and Vt
    const int mylim = 2 * qb + gid;
    const int lim = 2 * qb + 1;
    const int row0 = qb * 128 + gid * 64 + w4 * 16 + g;
    const int row1 = row0 + 8;
    const uint32_t smb = (uint32_t)__cvta_generic_to_shared(smh);

    // Q fragments direct from gmem (fp16). aq[kk] covers dims 16kk..16kk+15.
    uint32_t aq[4][4];
    {
        const __half* Q0 = g_Q + base + (size_t)row0 * HDIM;
        #pragma unroll
        for (int kk = 0; kk < 4; kk++) {
            int c = kk * 16 + 2 * tig;
            aq[kk][0] = *(const uint32_t*)&Q0[c];
            aq[kk][1] = *(const uint32_t*)&Q0[8 * HDIM + c];
            aq[kk][2] = *(const uint32_t*)&Q0[c + 8];
            aq[kk][3] = *(const uint32_t*)&Q0[8 * HDIM + c + 8];
        }
    }

    float oacc[8][4];
    #pragma unroll
    for (int ni = 0; ni < 8; ni++)
        #pragma unroll
        for (int j = 0; j < 4; j++) oacc[ni][j] = 0.f;
    float m0 = -1e30f, m1 = -1e30f, l0 = 0.f, l1 = 0.f;

    const __half* Kg  = g_K + base;
    const __half* Vtg = g_V + base;

    attn_load(smb, 0, Kg, Vtg, 0, tid);
    cpcommit();

    for (int kt = 0; kt <= lim; kt++) {
        const int s = kt & 1;
        if (kt < lim) {
            attn_load(smb, s ^ 1, Kg, Vtg, kt + 1, tid);
            cpcommit();
            cpwait<1>();
        } else {
            cpwait<0>();
        }
        __syncthreads();

        if (kt <= mylim) {
            const __half* Ks = smh + s * 4608;
            const __half* Vt = smh + 9216 + s * 4608;

            // S = Q @ K^T  (keys = n, dims = k)
            float sc[8][4];
            #pragma unroll
            for (int ni = 0; ni < 8; ni++)
                #pragma unroll
                for (int j = 0; j < 4; j++) sc[ni][j] = 0.f;
            #pragma unroll
            for (int kk = 0; kk < 4; kk++) {
                uint32_t b[8][2];
                #pragma unroll
                for (int ni = 0; ni < 8; ni++) {
                    int cb = (ni * 8 + g) * 72 + kk * 16 + 2 * tig;
                    b[ni][0] = *(const uint32_t*)&Ks[cb];
                    b[ni][1] = *(const uint32_t*)&Ks[cb + 8];
                }
                #pragma unroll
                for (int ni = 0; ni < 8; ni++) mmaf16(sc[ni], aq[kk], b[ni]);
            }

            // scale (log2 domain) + causal mask on diagonal tile + row max
            const bool diag = (kt == mylim);
            float nm0 = m0, nm1 = m1;
            #pragma unroll
            for (int ni = 0; ni < 8; ni++) {
                int col = kt * 64 + ni * 8 + 2 * tig;
                #pragma unroll
                for (int j = 0; j < 4; j++) sc[ni][j] *= SCL;
                if (diag) {
                    if (col     > row0) sc[ni][0] = -1e30f;
                    if (col + 1 > row0) sc[ni][1] = -1e30f;
                    if (col     > row1) sc[ni][2] = -1e30f;
                    if (col + 1 > row1) sc[ni][3] = -1e30f;
                }
                nm0 = fmaxf(nm0, fmaxf(sc[ni][0], sc[ni][1]));
                nm1 = fmaxf(nm1, fmaxf(sc[ni][2], sc[ni][3]));
            }
            nm0 = fmaxf(nm0, __shfl_xor_sync(0xffffffffu, nm0, 1));
            nm0 = fmaxf(nm0, __shfl_xor_sync(0xffffffffu, nm0, 2));
            nm1 = fmaxf(nm1, __shfl_xor_sync(0xffffffffu, nm1, 1));
            nm1 = fmaxf(nm1, __shfl_xor_sync(0xffffffffu, nm1, 2));
            const float corr0 = ex2(m0 - nm0), corr1 = ex2(m1 - nm1);
            m0 = nm0; m1 = nm1;

            // exp; P stays in registers (fp16 C->A fragment identity)
            float ps[8][4];
            float ls0 = 0.f, ls1 = 0.f;
            #pragma unroll
            for (int ni = 0; ni < 8; ni++) {
                ps[ni][0] = ex2(sc[ni][0] - m0);
                ps[ni][1] = ex2(sc[ni][1] - m0);
                ps[ni][2] = ex2(sc[ni][2] - m1);
                ps[ni][3] = ex2(sc[ni][3] - m1);
                ls0 += ps[ni][0] + ps[ni][1];
                ls1 += ps[ni][2] + ps[ni][3];
            }
            l0 = l0 * corr0 + ls0;
            l1 = l1 * corr1 + ls1;
            #pragma unroll
            for (int ni = 0; ni < 8; ni++) {
                oacc[ni][0] *= corr0; oacc[ni][1] *= corr0;
                oacc[ni][2] *= corr1; oacc[ni][3] *= corr1;
            }

            // O += P @ V  (dims = n via Vt rows, keys = k)
            #pragma unroll
            for (int kk = 0; kk < 4; kk++) {
                uint32_t pa[4];
                pa[0] = h2(ps[2*kk][0],   ps[2*kk][1]);
                pa[1] = h2(ps[2*kk][2],   ps[2*kk][3]);
                pa[2] = h2(ps[2*kk+1][0], ps[2*kk+1][1]);
                pa[3] = h2(ps[2*kk+1][2], ps[2*kk+1][3]);
                uint32_t b[8][2];
                #pragma unroll
                for (int ni = 0; ni < 8; ni++) {
                    int cb = (ni * 8 + g) * 72 + kk * 16 + 2 * tig;
                    b[ni][0] = *(const uint32_t*)&Vt[cb];
                    b[ni][1] = *(const uint32_t*)&Vt[cb + 8];
                }
                #pragma unroll
                for (int ni = 0; ni < 8; ni++) mmaf16(oacc[ni], pa, b[ni]);
            }
        }
        __syncthreads();
    }

    // Finalize
    l0 += __shfl_xor_sync(0xffffffffu, l0, 1);
    l0 += __shfl_xor_sync(0xffffffffu, l0, 2);
    l1 += __shfl_xor_sync(0xffffffffu, l1, 1);
    l1 += __shfl_xor_sync(0xffffffffu, l1, 2);
    const float i0 = 1.f / l0, i1 = 1.f / l1;
    const int b = bh >> 4, h = bh & 15;
    #pragma unroll
    for (int ni = 0; ni < 8; ni++) {
        int col = ni * 8 + 2 * tig;
        size_t o0 = ((size_t)(b * SS + row0)) * DD + h * HDIM + col;
        size_t o1 = ((size_t)(b * SS + row1)) * DD + h * HDIM + col;
        *(uint32_t*)&g_AO[o0] = h2(oacc[ni][0] * i0, oacc[ni][1] * i0);
        *(uint32_t*)&g_AO[o1] = h2(oacc[ni][2] * i1, oacc[ni][3] * i1);
    }
}

// ---------------------------------------------------------------------------
extern "C" void kernel_launch(void* const* d_in, const int* in_sizes, int n_in,
                              void* d_out, int out_size)
{
    const float* x  = (const float*)d_in[0];
    const float* fc = (const float*)d_in[1];
    const float* fs = (const float*)d_in[2];
    float* out = (float*)d_out;

    const int gemm_smem = 73728;
    const int attn_smem = 36864;
    cudaFuncSetAttribute(gemm_f16<0>, cudaFuncAttributeMaxDynamicSharedMemorySize, gemm_smem);
    cudaFuncSetAttribute(gemm_f16<1>, cudaFuncAttributeMaxDynamicSharedMemorySize, gemm_smem);
    cudaFuncSetAttribute(gemm_f16<2>, cudaFuncAttributeMaxDynamicSharedMemorySize, gemm_smem);
    cudaFuncSetAttribute(gemm_f16<3>, cudaFuncAttributeMaxDynamicSharedMemorySize, gemm_smem);
    cudaFuncSetAttribute(attn_f16,    cudaFuncAttributeMaxDynamicSharedMemorySize, attn_smem);

    const int n4x = MM * DD / 4;
    const int n4w = DD * DD / 4;
    cvt_k<0><<<n4x / 256, 256>>>((const float4*)x, n4x);
    cvt_k<1><<<n4w / 256, 256>>>((const float4*)d_in[3], n4w);
    cvt_k<2><<<n4w / 256, 256>>>((const float4*)d_in[4], n4w);
    cvt_k<3><<<n4w / 256, 256>>>((const float4*)d_in[5], n4w);
    cvt_k<4><<<n4w / 256, 256>>>((const float4*)d_in[6], n4w);

    dim3 gg(DD / 128, MM / 128);       // (8, 64)
    gemm_f16<0><<<gg, 256, gemm_smem>>>(fc, fs, nullptr);
    gemm_f16<1><<<gg, 256, gemm_smem>>>(fc, fs, nullptr);
    gemm_f16<2><<<gg, 256, gemm_smem>>>(fc, fs, nullptr);

    dim3 ag(SS / 128, BB * HH);        // (16, 64)
    attn_f16<<<ag, 256, attn_smem>>>();

    gemm_f16<3><<<gg, 256, gemm_smem>>>(nullptr, nullptr, out);
}